// round 8
// baseline (speedup 1.0000x reference)
#include <cuda_runtime.h>
#include <cuda_bf16.h>
#include <cstdint>

#define B_   4
#define T_   2048
#define C_   1024
#define H_   16
#define DH_  64
#define C3_  3072
#define M_   (B_*T_)      // 8192 rows
#define K_   1024

// ---------------------------------------------------------------------------
// Scratch (no cudaMalloc). xhi/xlo reused for attention output (disjoint liveness).
// ---------------------------------------------------------------------------
__device__ __nv_bfloat16 g_xhi[(size_t)M_ * C_];
__device__ __nv_bfloat16 g_xlo[(size_t)M_ * C_];
__device__ __nv_bfloat16 g_qkvh[(size_t)M_ * C3_];
__device__ __nv_bfloat16 g_qkvl[(size_t)M_ * C3_];
__device__ __nv_bfloat16 g_wqhi[(size_t)C3_ * C_];
__device__ __nv_bfloat16 g_wqlo[(size_t)C3_ * C_];
__device__ __nv_bfloat16 g_wohi[(size_t)C_ * C_];
__device__ __nv_bfloat16 g_wolo[(size_t)C_ * C_];

// ---------------------------------------------------------------------------
__device__ __forceinline__ uint32_t smem_u32(const void* p) {
    uint32_t a;
    asm("{ .reg .u64 t; cvta.to.shared.u64 t, %1; cvt.u32.u64 %0, t; }" : "=r"(a) : "l"(p));
    return a;
}
__device__ __forceinline__ void cpa16(uint32_t dst, const void* src) {
    asm volatile("cp.async.cg.shared.global [%0], [%1], 16;" :: "r"(dst), "l"(src));
}
__device__ __forceinline__ void ldm4(uint32_t* r, uint32_t addr) {
    asm volatile("ldmatrix.sync.aligned.m8n8.x4.shared.b16 {%0,%1,%2,%3}, [%4];"
                 : "=r"(r[0]), "=r"(r[1]), "=r"(r[2]), "=r"(r[3]) : "r"(addr));
}
__device__ __forceinline__ void ldm4t(uint32_t* r, uint32_t addr) {
    asm volatile("ldmatrix.sync.aligned.m8n8.x4.trans.shared.b16 {%0,%1,%2,%3}, [%4];"
                 : "=r"(r[0]), "=r"(r[1]), "=r"(r[2]), "=r"(r[3]) : "r"(addr));
}
__device__ __forceinline__ void mma16816(float* d, const uint32_t* a, const uint32_t* b) {
    asm volatile("mma.sync.aligned.m16n8k16.row.col.f32.bf16.bf16.f32 "
                 "{%0,%1,%2,%3}, {%4,%5,%6,%7}, {%8,%9}, {%0,%1,%2,%3};"
                 : "+f"(d[0]), "+f"(d[1]), "+f"(d[2]), "+f"(d[3])
                 : "r"(a[0]), "r"(a[1]), "r"(a[2]), "r"(a[3]), "r"(b[0]), "r"(b[1]));
}
__device__ __forceinline__ uint32_t pack_hi2(float a, float b) {
    uint32_t r;
    asm("prmt.b32 %0, %1, %2, 0x7632;" : "=r"(r)
        : "r"(__float_as_uint(a)), "r"(__float_as_uint(b)));
    return r;
}
__device__ __forceinline__ uint32_t pack_lo2(float a, float b) {
    float la = a - __uint_as_float(__float_as_uint(a) & 0xFFFF0000u);
    float lb = b - __uint_as_float(__float_as_uint(b) & 0xFFFF0000u);
    uint32_t r;
    asm("cvt.rn.bf16x2.f32 %0, %1, %2;" : "=r"(r) : "f"(lb), "f"(la));
    return r;
}

// ---------------------------------------------------------------------------
__global__ void split_f32(const float* __restrict__ x,
                          __nv_bfloat16* __restrict__ hi,
                          __nv_bfloat16* __restrict__ lo, int n)
{
    int i = blockIdx.x * blockDim.x + threadIdx.x;
    if (i < n) {
        float v = x[i];
        __nv_bfloat16 h = __float2bfloat16(v);
        hi[i] = h;
        lo[i] = __float2bfloat16(v - __bfloat162float(h));
    }
}

__global__ void splitT_f32(const float* __restrict__ W,
                           __nv_bfloat16* __restrict__ Thi,
                           __nv_bfloat16* __restrict__ Tlo, int K, int N)
{
    __shared__ float t[32][33];
    int n0 = blockIdx.x * 32, k0 = blockIdx.y * 32;
    int tx = threadIdx.x, ty = threadIdx.y;
    for (int r = ty; r < 32; r += 8)
        t[r][tx] = W[(size_t)(k0 + r) * N + n0 + tx];
    __syncthreads();
    for (int r = ty; r < 32; r += 8) {
        float v = t[tx][r];
        __nv_bfloat16 h = __float2bfloat16(v);
        size_t o = (size_t)(n0 + r) * K + k0 + tx;
        Thi[o] = h;
        Tlo[o] = __float2bfloat16(v - __bfloat162float(h));
    }
}

// ---------------------------------------------------------------------------
// mma.sync bf16x3 GEMM, CTA tile 128x64, 3 CTAs/SM (6 warps/SMSP).
// 8 warps as 4(M) x 2(N); warp tile 32x32; acc = 32 regs/thread.
// XOR-swizzled smem; 3-stage cp.async; 1 barrier/iter.
// ---------------------------------------------------------------------------
#define BKSLAB     32
#define AOPBg      8192                 // A operand/stage: 128 x 32 x 2B
#define BOPBg      4096                 // B operand/stage:  64 x 32 x 2B
#define STAGEB     (2 * AOPBg + 2 * BOPBg)   // 24576
#define GSTAGES    3
#define GEMM_SMEM  (GSTAGES * STAGEB)   // 73728 B -> 3 CTAs/SM

__global__ void __launch_bounds__(256, 3) gemm_mma(
    const __nv_bfloat16* __restrict__ Ahi, const __nv_bfloat16* __restrict__ Alo,
    const __nv_bfloat16* __restrict__ Bhi, const __nv_bfloat16* __restrict__ Blo,
    float* __restrict__ Cf, __nv_bfloat16* __restrict__ Chi,
    __nv_bfloat16* __restrict__ Clo, int N)
{
    extern __shared__ char smem[];
    const uint32_t sb = smem_u32(smem);
    const int tid  = threadIdx.x;
    const int m0   = blockIdx.y * 128;
    const int n0   = blockIdx.x * 64;
    const int wid  = tid >> 5, lane = tid & 31;
    const int warp_m = (wid & 3) * 32;
    const int warp_n = (wid >> 2) * 32;

    const __nv_bfloat16* pAh = Ahi + (size_t)m0 * K_;
    const __nv_bfloat16* pAl = Alo + (size_t)m0 * K_;
    const __nv_bfloat16* pBh = Bhi + (size_t)n0 * K_;
    const __nv_bfloat16* pBl = Blo + (size_t)n0 * K_;

    // per stage: Ah 512 chunks, Al 512, Bh 256, Bl 256 (16B each) = 6/thread
    auto load_stage = [&](int it, int slot) {
        const uint32_t st = sb + slot * STAGEB;
        const int kb = it * BKSLAB;
#pragma unroll
        for (int i = 0; i < 6; i++) {
            const __nv_bfloat16* base = (i < 2) ? pAh : (i < 4) ? pAl : (i == 4) ? pBh : pBl;
            const uint32_t opoff = (i < 2) ? 0u : (i < 4) ? (uint32_t)AOPBg
                                 : (i == 4) ? (uint32_t)(2 * AOPBg)
                                            : (uint32_t)(2 * AOPBg + BOPBg);
            const int ngrp = (i < 4) ? 16 : 8;        // line-groups per k-chunk col
            int w   = (i < 4) ? (((i & 1) << 8) + tid) : tid;
            int row = w >> 2;
            int c   = w & 3;
            const void* src = base + (size_t)row * K_ + kb + c * 8;
            uint32_t dst = st + opoff + (uint32_t)(c * ngrp + (row >> 3)) * 128
                         + (((row & 7) ^ (c << 1)) * 16);
            cpa16(dst, src);
        }
        asm volatile("cp.async.commit_group;" ::: "memory");
    };

    float acc[2][4][4];
#pragma unroll
    for (int a = 0; a < 2; a++)
#pragma unroll
        for (int b = 0; b < 4; b++)
#pragma unroll
            for (int c = 0; c < 4; c++) acc[a][b][c] = 0.f;

    const int mA  = warp_m + (lane & 15);
    const int mA8 = mA >> 3, mA7 = mA & 7;
    const int k8A = lane >> 4;
    const int nB  = warp_n + ((lane >> 4) << 3) + (lane & 7);
    const int nB8 = nB >> 3, nB7 = nB & 7;
    const int k8B = (lane >> 3) & 1;

    load_stage(0, 0);
    load_stage(1, 1);

    const int NIT = K_ / BKSLAB;
    for (int it = 0; it < NIT; it++) {
        if (it + 1 < NIT) asm volatile("cp.async.wait_group 1;" ::: "memory");
        else              asm volatile("cp.async.wait_group 0;" ::: "memory");
        __syncthreads();
        if (it + 2 < NIT) load_stage(it + 2, (it + 2) % GSTAGES);

        const uint32_t st = sb + (it % GSTAGES) * STAGEB;
        const uint32_t AH = st, AL = st + AOPBg;
        const uint32_t BH = st + 2 * AOPBg, BL = st + 2 * AOPBg + BOPBg;

#pragma unroll
        for (int ks = 0; ks < 2; ks++) {
            const int cA = ks * 2 + k8A;
            const int cB = ks * 2 + k8B;
            const uint32_t offA = (uint32_t)(cA * 16 + mA8) * 128 + ((mA7 ^ (cA << 1)) * 16);
            const uint32_t offB = (uint32_t)(cB * 8 + nB8) * 128 + ((nB7 ^ (cB << 1)) * 16);

            uint32_t ah[2][4], bb[4][2];
            ldm4(ah[0], AH + offA);
            ldm4(ah[1], AH + offA + 256);
            ldm4(&bb[0][0], BH + offB);
            ldm4(&bb[2][0], BH + offB + 256);
            // Ah x Bh
#pragma unroll
            for (int mt = 0; mt < 2; mt++)
#pragma unroll
                for (int nt = 0; nt < 4; nt++) mma16816(acc[mt][nt], ah[mt], bb[nt]);
            // Al x Bh (streamed)
#pragma unroll
            for (int mt = 0; mt < 2; mt++) {
                uint32_t al[4];
                ldm4(al, AL + offA + mt * 256);
#pragma unroll
                for (int nt = 0; nt < 4; nt++) mma16816(acc[mt][nt], al, bb[nt]);
            }
            // Ah x Bl (overwrite B fragments)
            ldm4(&bb[0][0], BL + offB);
            ldm4(&bb[2][0], BL + offB + 256);
#pragma unroll
            for (int mt = 0; mt < 2; mt++)
#pragma unroll
                for (int nt = 0; nt < 4; nt++) mma16816(acc[mt][nt], ah[mt], bb[nt]);
        }
    }

    const int r0 = m0 + warp_m + (lane >> 2);
    const int c0 = n0 + warp_n + (lane & 3) * 2;
    if (Chi) {
#pragma unroll
        for (int mt = 0; mt < 2; mt++) {
#pragma unroll
            for (int nt = 0; nt < 4; nt++) {
                size_t o0 = (size_t)(r0 + mt * 16) * N + c0 + nt * 8;
                size_t o1 = o0 + (size_t)8 * N;
                *(uint32_t*)(Chi + o0) = pack_hi2(acc[mt][nt][0], acc[mt][nt][1]);
                *(uint32_t*)(Clo + o0) = pack_lo2(acc[mt][nt][0], acc[mt][nt][1]);
                *(uint32_t*)(Chi + o1) = pack_hi2(acc[mt][nt][2], acc[mt][nt][3]);
                *(uint32_t*)(Clo + o1) = pack_lo2(acc[mt][nt][2], acc[mt][nt][3]);
            }
        }
    } else {
#pragma unroll
        for (int mt = 0; mt < 2; mt++) {
#pragma unroll
            for (int nt = 0; nt < 4; nt++) {
                float* p = Cf + (size_t)(r0 + mt * 16) * N + c0 + nt * 8;
                *(float2*)p                   = make_float2(acc[mt][nt][0], acc[mt][nt][1]);
                *(float2*)(p + (size_t)8 * N) = make_float2(acc[mt][nt][2], acc[mt][nt][3]);
            }
        }
    }
}

// ---------------------------------------------------------------------------
// Tensor-core flash attention, split-bf16 x3, causal + ALiBi (unchanged).
// ---------------------------------------------------------------------------
#define AQT       128
#define AKT       64
#define AOPB      8192
#define ASTAGEB   (4 * AOPB)
#define ATT_SMEM  (32768 + 2 * ASTAGEB)  // 98304 B

__global__ void __launch_bounds__(256, 2) attn_mma(
    const __nv_bfloat16* __restrict__ qkvh, const __nv_bfloat16* __restrict__ qkvl,
    __nv_bfloat16* __restrict__ oh, __nv_bfloat16* __restrict__ ol)
{
    extern __shared__ char smem[];
    const uint32_t sb = smem_u32(smem);
    const uint32_t Qh = sb, Ql = sb + 16384;
    const uint32_t ST0 = sb + 32768;

    const int tid  = threadIdx.x;
    const int wid  = tid >> 5, lane = tid & 31;
    const int b    = blockIdx.z;
    const int h    = blockIdx.y;
    const int qt   = blockIdx.x;
    const int q0   = qt * AQT;
    const int nkt  = 2 * qt + 2;
    const size_t rbase = (size_t)b * T_;

    const float LOG2E = 1.4426950408889634f;
    const float sc2 = LOG2E / 32.0f;
    const float sl2 = exp2f(-0.5f * (float)(h + 1)) * LOG2E;

    for (int i = tid; i < 2048; i += 256) {
        int arr = i >> 10, r = (i >> 3) & 127, c8 = i & 7;
        const __nv_bfloat16* g = arr ? qkvl : qkvh;
        const void* src = g + (rbase + q0 + r) * C3_ + h * DH_ + c8 * 8;
        uint32_t dst = (arr ? Ql : Qh) + (c8 * 16 + (r >> 3)) * 128 + (((r & 7) ^ c8) * 16);
        cpa16(dst, src);
    }
    auto load_stage = [&](int kt, int slot) {
        const int k0 = kt * AKT;
        const uint32_t st = ST0 + slot * ASTAGEB;
        for (int i = tid; i < 2048; i += 256) {
            int op = i >> 9, r = (i >> 3) & 63, c8 = i & 7;
            const __nv_bfloat16* g = (op & 1) ? qkvl : qkvh;
            int coloff = ((op < 2) ? C_ : 2 * C_) + h * DH_;
            const void* src = g + (rbase + k0 + r) * C3_ + coloff + c8 * 8;
            uint32_t dst = st + op * AOPB + (c8 * 8 + (r >> 3)) * 128 + (((r & 7) ^ c8) * 16);
            cpa16(dst, src);
        }
        asm volatile("cp.async.commit_group;" ::: "memory");
    };
    load_stage(0, 0);

    float oacc[8][4];
#pragma unroll
    for (int j = 0; j < 8; j++)
#pragma unroll
        for (int c = 0; c < 4; c++) oacc[j][c] = 0.f;
    float m0r = -1e30f, m1r = -1e30f, l0 = 0.f, l1 = 0.f;

    const int rA   = wid * 16 + (lane & 15);
    const int rA8  = rA >> 3, rA7 = rA & 7;
    const int qc8h = lane >> 4;
    const int nKl  = (lane & 7) + ((lane >> 4) << 3);
    const int kc8h = (lane >> 3) & 1;
    const int rVl  = (lane & 7) + (((lane >> 3) & 1) << 3);
    const int vc8h = lane >> 4;
    const int row0 = q0 + wid * 16 + (lane >> 2);
    const int row1 = row0 + 8;

    for (int kt = 0; kt < nkt; kt++) {
        asm volatile("cp.async.wait_group 0;" ::: "memory");
        __syncthreads();
        if (kt + 1 < nkt) load_stage(kt + 1, (kt + 1) & 1);

        const int k0 = kt * AKT;
        const uint32_t st = ST0 + (kt & 1) * ASTAGEB;
        const uint32_t Kh = st, Kl = st + AOPB, Vh = st + 2 * AOPB, Vl = st + 3 * AOPB;

        float sacc[8][4];
#pragma unroll
        for (int j = 0; j < 8; j++)
#pragma unroll
            for (int c = 0; c < 4; c++) sacc[j][c] = 0.f;

#pragma unroll
        for (int ks = 0; ks < 4; ks++) {
            const int cq = 2 * ks + qc8h;
            const int ck = 2 * ks + kc8h;
            uint32_t qfh[4], qfl[4];
            const uint32_t qoff = (uint32_t)(cq * 16 + rA8) * 128 + ((rA7 ^ cq) * 16);
            ldm4(qfh, Qh + qoff);
            ldm4(qfl, Ql + qoff);
#pragma unroll
            for (int j = 0; j < 4; j++) {
                uint32_t kfh[4], kfl[4];
                const int rowK = 16 * j + nKl;
                const uint32_t koff = (uint32_t)(ck * 8 + (rowK >> 3)) * 128
                                    + (((rowK & 7) ^ ck) * 16);
                ldm4(kfh, Kh + koff);
                ldm4(kfl, Kl + koff);
                mma16816(sacc[2 * j],     qfh, kfh);
                mma16816(sacc[2 * j + 1], qfh, kfh + 2);
                mma16816(sacc[2 * j],     qfh, kfl);
                mma16816(sacc[2 * j + 1], qfh, kfl + 2);
                mma16816(sacc[2 * j],     qfl, kfh);
                mma16816(sacc[2 * j + 1], qfl, kfh + 2);
            }
        }

        float mx0 = -1e30f, mx1 = -1e30f;
#pragma unroll
        for (int j = 0; j < 8; j++) {
            int col = k0 + j * 8 + (lane & 3) * 2;
            float s0 = (col     <= row0) ? sacc[j][0] * sc2 + sl2 * (float)(col     - row0) : -1e30f;
            float s1 = (col + 1 <= row0) ? sacc[j][1] * sc2 + sl2 * (float)(col + 1 - row0) : -1e30f;
            float s2 = (col     <= row1) ? sacc[j][2] * sc2 + sl2 * (float)(col     - row1) : -1e30f;
            float s3 = (col + 1 <= row1) ? sacc[j][3] * sc2 + sl2 * (float)(col + 1 - row1) : -1e30f;
            sacc[j][0] = s0; sacc[j][1] = s1; sacc[j][2] = s2; sacc[j][3] = s3;
            mx0 = fmaxf(mx0, fmaxf(s0, s1));
            mx1 = fmaxf(mx1, fmaxf(s2, s3));
        }
        mx0 = fmaxf(mx0, __shfl_xor_sync(0xFFFFFFFFu, mx0, 1));
        mx0 = fmaxf(mx0, __shfl_xor_sync(0xFFFFFFFFu, mx0, 2));
        mx1 = fmaxf(mx1, __shfl_xor_sync(0xFFFFFFFFu, mx1, 1));
        mx1 = fmaxf(mx1, __shfl_xor_sync(0xFFFFFFFFu, mx1, 2));
        float mn0 = fmaxf(m0r, mx0), mn1 = fmaxf(m1r, mx1);
        float cr0 = exp2f(m0r - mn0), cr1 = exp2f(m1r - mn1);
        m0r = mn0; m1r = mn1;
        l0 *= cr0; l1 *= cr1;
#pragma unroll
        for (int j = 0; j < 8; j++) {
            float p0 = exp2f(sacc[j][0] - mn0);
            float p1 = exp2f(sacc[j][1] - mn0);
            float p2 = exp2f(sacc[j][2] - mn1);
            float p3 = exp2f(sacc[j][3] - mn1);
            l0 += p0 + p1; l1 += p2 + p3;
            sacc[j][0] = p0; sacc[j][1] = p1; sacc[j][2] = p2; sacc[j][3] = p3;
        }
#pragma unroll
        for (int j = 0; j < 8; j++) {
            oacc[j][0] *= cr0; oacc[j][1] *= cr0;
            oacc[j][2] *= cr1; oacc[j][3] *= cr1;
        }

        uint32_t pah[4][4], pal[4][4];
#pragma unroll
        for (int t = 0; t < 4; t++) {
            pah[t][0] = pack_hi2(sacc[2 * t][0],     sacc[2 * t][1]);
            pah[t][1] = pack_hi2(sacc[2 * t][2],     sacc[2 * t][3]);
            pah[t][2] = pack_hi2(sacc[2 * t + 1][0], sacc[2 * t + 1][1]);
            pah[t][3] = pack_hi2(sacc[2 * t + 1][2], sacc[2 * t + 1][3]);
            pal[t][0] = pack_lo2(sacc[2 * t][0],     sacc[2 * t][1]);
            pal[t][1] = pack_lo2(sacc[2 * t][2],     sacc[2 * t][3]);
            pal[t][2] = pack_lo2(sacc[2 * t + 1][0], sacc[2 * t + 1][1]);
            pal[t][3] = pack_lo2(sacc[2 * t + 1][2], sacc[2 * t + 1][3]);
        }

#pragma unroll
        for (int g = 0; g < 4; g++) {
            const int cv = 2 * g + vc8h;
#pragma unroll
            for (int ks = 0; ks < 4; ks++) {
                uint32_t vfh[4], vfl[4];
                const int rowV = 16 * ks + rVl;
                const uint32_t voff = (uint32_t)(cv * 8 + (rowV >> 3)) * 128
                                    + (((rowV & 7) ^ cv) * 16);
                ldm4t(vfh, Vh + voff);
                ldm4t(vfl, Vl + voff);
                mma16816(oacc[2 * g],     pah[ks], vfh);
                mma16816(oacc[2 * g + 1], pah[ks], vfh + 2);
                mma16816(oacc[2 * g],     pah[ks], vfl);
                mma16816(oacc[2 * g + 1], pah[ks], vfl + 2);
                mma16816(oacc[2 * g],     pal[ks], vfh);
                mma16816(oacc[2 * g + 1], pal[ks], vfh + 2);
            }
        }
    }

    l0 += __shfl_xor_sync(0xFFFFFFFFu, l0, 1);
    l0 += __shfl_xor_sync(0xFFFFFFFFu, l0, 2);
    l1 += __shfl_xor_sync(0xFFFFFFFFu, l1, 1);
    l1 += __shfl_xor_sync(0xFFFFFFFFu, l1, 2);
    const float iv0 = 1.0f / l0, iv1 = 1.0f / l1;
    const size_t gr0 = (rbase + row0) * C_;
    const size_t gr1 = (rbase + row1) * C_;
#pragma unroll
    for (int j = 0; j < 8; j++) {
        int col = h * DH_ + j * 8 + (lane & 3) * 2;
        float o0 = oacc[j][0] * iv0, o1 = oacc[j][1] * iv0;
        float o2 = oacc[j][2] * iv1, o3 = oacc[j][3] * iv1;
        *(uint32_t*)(oh + gr0 + col) = pack_hi2(o0, o1);
        *(uint32_t*)(ol + gr0 + col) = pack_lo2(o0, o1);
        *(uint32_t*)(oh + gr1 + col) = pack_hi2(o2, o3);
        *(uint32_t*)(ol + gr1 + col) = pack_lo2(o2, o3);
    }
}

// ---------------------------------------------------------------------------
extern "C" void kernel_launch(void* const* d_in, const int* in_sizes, int n_in,
                              void* d_out, int out_size)
{
    const float* x     = (const float*)d_in[0];
    const float* w_qkv = (const float*)d_in[1];
    const float* w_o   = (const float*)d_in[2];
    float* out = (float*)d_out;

    __nv_bfloat16 *xhi, *xlo, *qkvh, *qkvl, *wqhi, *wqlo, *wohi, *wolo;
    cudaGetSymbolAddress((void**)&xhi,  g_xhi);
    cudaGetSymbolAddress((void**)&xlo,  g_xlo);
    cudaGetSymbolAddress((void**)&qkvh, g_qkvh);
    cudaGetSymbolAddress((void**)&qkvl, g_qkvl);
    cudaGetSymbolAddress((void**)&wqhi, g_wqhi);
    cudaGetSymbolAddress((void**)&wqlo, g_wqlo);
    cudaGetSymbolAddress((void**)&wohi, g_wohi);
    cudaGetSymbolAddress((void**)&wolo, g_wolo);

    cudaFuncSetAttribute(gemm_mma, cudaFuncAttributeMaxDynamicSharedMemorySize, GEMM_SMEM);
    cudaFuncSetAttribute(attn_mma, cudaFuncAttributeMaxDynamicSharedMemorySize, ATT_SMEM);

    split_f32<<<(M_ * C_ + 255) / 256, 256>>>(x, xhi, xlo, M_ * C_);
    splitT_f32<<<dim3(C3_ / 32, C_ / 32), dim3(32, 8)>>>(w_qkv, wqhi, wqlo, C_, C3_);
    splitT_f32<<<dim3(C_ / 32,  C_ / 32), dim3(32, 8)>>>(w_o,   wohi, wolo, C_, C_);

    gemm_mma<<<dim3(C3_ / 64, M_ / 128), 256, GEMM_SMEM>>>(
        xhi, xlo, wqhi, wqlo, nullptr, qkvh, qkvl, C3_);

    attn_mma<<<dim3(T_ / AQT, H_, B_), 256, ATT_SMEM>>>(qkvh, qkvl, xhi, xlo);

    gemm_mma<<<dim3(C_ / 64, M_ / 128), 256, GEMM_SMEM>>>(
        xhi, xlo, wohi, wolo, out, nullptr, nullptr, C_);
}

// round 9
// speedup vs baseline: 1.1932x; 1.1932x over previous
#include <cuda_runtime.h>
#include <cuda_bf16.h>
#include <cstdint>

#define B_   4
#define T_   2048
#define C_   1024
#define H_   16
#define DH_  64
#define C3_  3072
#define M_   (B_*T_)      // 8192 rows
#define K_   1024

// ---------------------------------------------------------------------------
// Scratch (no cudaMalloc). xhi/xlo reused for attention output (disjoint liveness).
// ---------------------------------------------------------------------------
__device__ __nv_bfloat16 g_xhi[(size_t)M_ * C_];
__device__ __nv_bfloat16 g_xlo[(size_t)M_ * C_];
__device__ __nv_bfloat16 g_qkvh[(size_t)M_ * C3_];
__device__ __nv_bfloat16 g_qkvl[(size_t)M_ * C3_];
__device__ __nv_bfloat16 g_wqhi[(size_t)C3_ * C_];
__device__ __nv_bfloat16 g_wqlo[(size_t)C3_ * C_];
__device__ __nv_bfloat16 g_wohi[(size_t)C_ * C_];
__device__ __nv_bfloat16 g_wolo[(size_t)C_ * C_];

// ---------------------------------------------------------------------------
__device__ __forceinline__ uint32_t smem_u32(const void* p) {
    uint32_t a;
    asm("{ .reg .u64 t; cvta.to.shared.u64 t, %1; cvt.u32.u64 %0, t; }" : "=r"(a) : "l"(p));
    return a;
}
__device__ __forceinline__ void cpa16(uint32_t dst, const void* src) {
    asm volatile("cp.async.cg.shared.global [%0], [%1], 16;" :: "r"(dst), "l"(src));
}
__device__ __forceinline__ void ldm4(uint32_t* r, uint32_t addr) {
    asm volatile("ldmatrix.sync.aligned.m8n8.x4.shared.b16 {%0,%1,%2,%3}, [%4];"
                 : "=r"(r[0]), "=r"(r[1]), "=r"(r[2]), "=r"(r[3]) : "r"(addr));
}
__device__ __forceinline__ void ldm4t(uint32_t* r, uint32_t addr) {
    asm volatile("ldmatrix.sync.aligned.m8n8.x4.trans.shared.b16 {%0,%1,%2,%3}, [%4];"
                 : "=r"(r[0]), "=r"(r[1]), "=r"(r[2]), "=r"(r[3]) : "r"(addr));
}
__device__ __forceinline__ void mma16816(float* d, const uint32_t* a, const uint32_t* b) {
    asm volatile("mma.sync.aligned.m16n8k16.row.col.f32.bf16.bf16.f32 "
                 "{%0,%1,%2,%3}, {%4,%5,%6,%7}, {%8,%9}, {%0,%1,%2,%3};"
                 : "+f"(d[0]), "+f"(d[1]), "+f"(d[2]), "+f"(d[3])
                 : "r"(a[0]), "r"(a[1]), "r"(a[2]), "r"(a[3]), "r"(b[0]), "r"(b[1]));
}
// RN-rounded hi pair (a in low bf16, b in high)
__device__ __forceinline__ uint32_t pack_rn_hi2(float a, float b) {
    uint32_t r;
    asm("cvt.rn.bf16x2.f32 %0, %1, %2;" : "=r"(r) : "f"(b), "f"(a));
    return r;
}
// residual pair against an RN hi pack
__device__ __forceinline__ uint32_t pack_rn_lo2(float a, float b, uint32_t hi) {
    float ha = __uint_as_float(hi << 16);
    float hb = __uint_as_float(hi & 0xFFFF0000u);
    uint32_t r;
    asm("cvt.rn.bf16x2.f32 %0, %1, %2;" : "=r"(r) : "f"(b - hb), "f"(a - ha));
    return r;
}

// ---------------------------------------------------------------------------
__global__ void split_f32(const float* __restrict__ x,
                          __nv_bfloat16* __restrict__ hi,
                          __nv_bfloat16* __restrict__ lo, int n)
{
    int i = blockIdx.x * blockDim.x + threadIdx.x;
    if (i < n) {
        float v = x[i];
        __nv_bfloat16 h = __float2bfloat16(v);
        hi[i] = h;
        lo[i] = __float2bfloat16(v - __bfloat162float(h));
    }
}

__global__ void splitT_f32(const float* __restrict__ W,
                           __nv_bfloat16* __restrict__ Thi,
                           __nv_bfloat16* __restrict__ Tlo, int K, int N)
{
    __shared__ float t[32][33];
    int n0 = blockIdx.x * 32, k0 = blockIdx.y * 32;
    int tx = threadIdx.x, ty = threadIdx.y;
    for (int r = ty; r < 32; r += 8)
        t[r][tx] = W[(size_t)(k0 + r) * N + n0 + tx];
    __syncthreads();
    for (int r = ty; r < 32; r += 8) {
        float v = t[tx][r];
        __nv_bfloat16 h = __float2bfloat16(v);
        size_t o = (size_t)(n0 + r) * K + k0 + tx;
        Thi[o] = h;
        Tlo[o] = __float2bfloat16(v - __bfloat162float(h));
    }
}

// ---------------------------------------------------------------------------
// mma.sync split-bf16 GEMM, 128x128 CTA tile (best-measured R7 geometry).
// nprod==3: Ah*Bh + Al*Bh + Ah*Bl.  nprod==2: Ah*Bh + Ah*Bl (Al never loaded).
// ---------------------------------------------------------------------------
#define BKSLAB     32
#define OPB        8192
#define STAGEB     (4 * OPB)
#define GSTAGES    3
#define GEMM_SMEM  (GSTAGES * STAGEB)   // 98304 B

__global__ void __launch_bounds__(256, 2) gemm_mma(
    const __nv_bfloat16* __restrict__ Ahi, const __nv_bfloat16* __restrict__ Alo,
    const __nv_bfloat16* __restrict__ Bhi, const __nv_bfloat16* __restrict__ Blo,
    float* __restrict__ Cf, __nv_bfloat16* __restrict__ Chi,
    __nv_bfloat16* __restrict__ Clo, int N, int nprod)
{
    extern __shared__ char smem[];
    const uint32_t sb = smem_u32(smem);
    const int tid  = threadIdx.x;
    const int m0   = blockIdx.y * 128;
    const int n0   = blockIdx.x * 128;
    const int wid  = tid >> 5, lane = tid & 31;
    const int warp_m = (wid & 1) * 64;
    const int warp_n = (wid >> 1) * 32;

    const __nv_bfloat16* pAh = Ahi + (size_t)m0 * K_;
    const __nv_bfloat16* pAl = Alo + (size_t)m0 * K_;
    const __nv_bfloat16* pBh = Bhi + (size_t)n0 * K_;
    const __nv_bfloat16* pBl = Blo + (size_t)n0 * K_;

    auto load_stage = [&](int it, int slot) {
        const uint32_t st = sb + slot * STAGEB;
        const int kb = it * BKSLAB;
#pragma unroll
        for (int i = 0; i < 8; i++) {
            if ((i == 2 || i == 3) && nprod == 2) continue;   // Al unused
            const __nv_bfloat16* base = (i < 2) ? pAh : (i < 4) ? pAl : (i < 6) ? pBh : pBl;
            int w   = ((i & 1) << 8) + tid;
            int row = w >> 2;
            int c   = w & 3;
            const void* src = base + (size_t)row * K_ + kb + c * 8;
            uint32_t dst = st + (i >> 1) * OPB + (c * 16 + (row >> 3)) * 128
                         + (((row & 7) ^ (c << 1)) * 16);
            cpa16(dst, src);
        }
        asm volatile("cp.async.commit_group;" ::: "memory");
    };

    float acc[4][4][4];
#pragma unroll
    for (int a = 0; a < 4; a++)
#pragma unroll
        for (int b = 0; b < 4; b++)
#pragma unroll
            for (int c = 0; c < 4; c++) acc[a][b][c] = 0.f;

    const int mA  = warp_m + (lane & 15);
    const int mA8 = mA >> 3, mA7 = mA & 7;
    const int k8A = lane >> 4;
    const int nB  = warp_n + ((lane >> 4) << 3) + (lane & 7);
    const int nB8 = nB >> 3, nB7 = nB & 7;
    const int k8B = (lane >> 3) & 1;

    load_stage(0, 0);
    load_stage(1, 1);

    const int NIT = K_ / BKSLAB;
    for (int it = 0; it < NIT; it++) {
        if (it + 1 < NIT) asm volatile("cp.async.wait_group 1;" ::: "memory");
        else              asm volatile("cp.async.wait_group 0;" ::: "memory");
        __syncthreads();
        if (it + 2 < NIT) load_stage(it + 2, (it + 2) % GSTAGES);

        const uint32_t st = sb + (it % GSTAGES) * STAGEB;
        const uint32_t AH = st, AL = st + OPB, BH = st + 2 * OPB, BL = st + 3 * OPB;

#pragma unroll
        for (int ks = 0; ks < 2; ks++) {
            const int cA = ks * 2 + k8A;
            const int cB = ks * 2 + k8B;
            const uint32_t offA = (uint32_t)(cA * 16 + mA8) * 128 + ((mA7 ^ (cA << 1)) * 16);
            const uint32_t offB = (uint32_t)(cB * 16 + nB8) * 128 + ((nB7 ^ (cB << 1)) * 16);

            uint32_t ah[4][4], bb[4][2];
#pragma unroll
            for (int mt = 0; mt < 4; mt++)
                ldm4(ah[mt], AH + offA + mt * 256);
#pragma unroll
            for (int j = 0; j < 2; j++)
                ldm4(&bb[j * 2][0], BH + offB + j * 256);
            // Ah x Bh
#pragma unroll
            for (int mt = 0; mt < 4; mt++)
#pragma unroll
                for (int nt = 0; nt < 4; nt++) mma16816(acc[mt][nt], ah[mt], bb[nt]);
            // Al x Bh (3-product only; streamed one m-stripe at a time)
            if (nprod == 3) {
#pragma unroll
                for (int mt = 0; mt < 4; mt++) {
                    uint32_t al[4];
                    ldm4(al, AL + offA + mt * 256);
#pragma unroll
                    for (int nt = 0; nt < 4; nt++) mma16816(acc[mt][nt], al, bb[nt]);
                }
            }
            // Ah x Bl (overwrite B fragments)
#pragma unroll
            for (int j = 0; j < 2; j++)
                ldm4(&bb[j * 2][0], BL + offB + j * 256);
#pragma unroll
            for (int mt = 0; mt < 4; mt++)
#pragma unroll
                for (int nt = 0; nt < 4; nt++) mma16816(acc[mt][nt], ah[mt], bb[nt]);
        }
    }

    const int r0 = m0 + warp_m + (lane >> 2);
    const int c0 = n0 + warp_n + (lane & 3) * 2;
    if (Chi) {
#pragma unroll
        for (int mt = 0; mt < 4; mt++) {
#pragma unroll
            for (int nt = 0; nt < 4; nt++) {
                size_t o0 = (size_t)(r0 + mt * 16) * N + c0 + nt * 8;
                size_t o1 = o0 + (size_t)8 * N;
                uint32_t h0 = pack_rn_hi2(acc[mt][nt][0], acc[mt][nt][1]);
                uint32_t h1 = pack_rn_hi2(acc[mt][nt][2], acc[mt][nt][3]);
                *(uint32_t*)(Chi + o0) = h0;
                *(uint32_t*)(Clo + o0) = pack_rn_lo2(acc[mt][nt][0], acc[mt][nt][1], h0);
                *(uint32_t*)(Chi + o1) = h1;
                *(uint32_t*)(Clo + o1) = pack_rn_lo2(acc[mt][nt][2], acc[mt][nt][3], h1);
            }
        }
    } else {
#pragma unroll
        for (int mt = 0; mt < 4; mt++) {
#pragma unroll
            for (int nt = 0; nt < 4; nt++) {
                float* p = Cf + (size_t)(r0 + mt * 16) * N + c0 + nt * 8;
                *(float2*)p                   = make_float2(acc[mt][nt][0], acc[mt][nt][1]);
                *(float2*)(p + (size_t)8 * N) = make_float2(acc[mt][nt][2], acc[mt][nt][3]);
            }
        }
    }
}

// ---------------------------------------------------------------------------
// Tensor-core flash attention, causal + ALiBi.
// QK^T: 2-product (Qh*Kh + Qh*Kl) — Q residual dropped (error ~6e-5 on probs).
// PV:   3-product (Ph*Vh + Ph*Vl + Pl*Vh) — output-linear, keeps accuracy.
// ---------------------------------------------------------------------------
#define AQT       128
#define AKT       64
#define AOPB      8192
#define ASTAGEB   (4 * AOPB)
#define ATT_SMEM  (32768 + 2 * ASTAGEB)  // 98304 B

__global__ void __launch_bounds__(256, 2) attn_mma(
    const __nv_bfloat16* __restrict__ qkvh, const __nv_bfloat16* __restrict__ qkvl,
    __nv_bfloat16* __restrict__ oh, __nv_bfloat16* __restrict__ ol)
{
    extern __shared__ char smem[];
    const uint32_t sb = smem_u32(smem);
    const uint32_t Qh = sb, Ql = sb + 16384;   // Ql slot unused now (kept for layout)
    const uint32_t ST0 = sb + 32768;

    const int tid  = threadIdx.x;
    const int wid  = tid >> 5, lane = tid & 31;
    const int b    = blockIdx.z;
    const int h    = blockIdx.y;
    const int qt   = blockIdx.x;
    const int q0   = qt * AQT;
    const int nkt  = 2 * qt + 2;
    const size_t rbase = (size_t)b * T_;

    const float LOG2E = 1.4426950408889634f;
    const float sc2 = LOG2E / 32.0f;
    const float sl2 = exp2f(-0.5f * (float)(h + 1)) * LOG2E;

    // Q tile (hi only needed now)
    for (int i = tid; i < 1024; i += 256) {
        int r = (i >> 3) & 127, c8 = i & 7;
        const void* src = qkvh + (rbase + q0 + r) * C3_ + h * DH_ + c8 * 8;
        uint32_t dst = Qh + (c8 * 16 + (r >> 3)) * 128 + (((r & 7) ^ c8) * 16);
        cpa16(dst, src);
    }
    (void)Ql;
    auto load_stage = [&](int kt, int slot) {
        const int k0 = kt * AKT;
        const uint32_t st = ST0 + slot * ASTAGEB;
        for (int i = tid; i < 2048; i += 256) {
            int op = i >> 9, r = (i >> 3) & 63, c8 = i & 7;
            const __nv_bfloat16* g = (op & 1) ? qkvl : qkvh;
            int coloff = ((op < 2) ? C_ : 2 * C_) + h * DH_;
            const void* src = g + (rbase + k0 + r) * C3_ + coloff + c8 * 8;
            uint32_t dst = st + op * AOPB + (c8 * 8 + (r >> 3)) * 128 + (((r & 7) ^ c8) * 16);
            cpa16(dst, src);
        }
        asm volatile("cp.async.commit_group;" ::: "memory");
    };
    load_stage(0, 0);

    float oacc[8][4];
#pragma unroll
    for (int j = 0; j < 8; j++)
#pragma unroll
        for (int c = 0; c < 4; c++) oacc[j][c] = 0.f;
    float m0r = -1e30f, m1r = -1e30f, l0 = 0.f, l1 = 0.f;

    const int rA   = wid * 16 + (lane & 15);
    const int rA8  = rA >> 3, rA7 = rA & 7;
    const int qc8h = lane >> 4;
    const int nKl  = (lane & 7) + ((lane >> 4) << 3);
    const int kc8h = (lane >> 3) & 1;
    const int rVl  = (lane & 7) + (((lane >> 3) & 1) << 3);
    const int vc8h = lane >> 4;
    const int row0 = q0 + wid * 16 + (lane >> 2);
    const int row1 = row0 + 8;

    for (int kt = 0; kt < nkt; kt++) {
        asm volatile("cp.async.wait_group 0;" ::: "memory");
        __syncthreads();
        if (kt + 1 < nkt) load_stage(kt + 1, (kt + 1) & 1);

        const int k0 = kt * AKT;
        const uint32_t st = ST0 + (kt & 1) * ASTAGEB;
        const uint32_t Kh = st, Kl = st + AOPB, Vh = st + 2 * AOPB, Vl = st + 3 * AOPB;

        float sacc[8][4];
#pragma unroll
        for (int j = 0; j < 8; j++)
#pragma unroll
            for (int c = 0; c < 4; c++) sacc[j][c] = 0.f;

#pragma unroll
        for (int ks = 0; ks < 4; ks++) {
            const int cq = 2 * ks + qc8h;
            const int ck = 2 * ks + kc8h;
            uint32_t qfh[4];
            const uint32_t qoff = (uint32_t)(cq * 16 + rA8) * 128 + ((rA7 ^ cq) * 16);
            ldm4(qfh, Qh + qoff);
#pragma unroll
            for (int j = 0; j < 4; j++) {
                uint32_t kfh[4], kfl[4];
                const int rowK = 16 * j + nKl;
                const uint32_t koff = (uint32_t)(ck * 8 + (rowK >> 3)) * 128
                                    + (((rowK & 7) ^ ck) * 16);
                ldm4(kfh, Kh + koff);
                ldm4(kfl, Kl + koff);
                mma16816(sacc[2 * j],     qfh, kfh);
                mma16816(sacc[2 * j + 1], qfh, kfh + 2);
                mma16816(sacc[2 * j],     qfh, kfl);
                mma16816(sacc[2 * j + 1], qfh, kfl + 2);
            }
        }

        float mx0 = -1e30f, mx1 = -1e30f;
#pragma unroll
        for (int j = 0; j < 8; j++) {
            int col = k0 + j * 8 + (lane & 3) * 2;
            float s0 = (col     <= row0) ? sacc[j][0] * sc2 + sl2 * (float)(col     - row0) : -1e30f;
            float s1 = (col + 1 <= row0) ? sacc[j][1] * sc2 + sl2 * (float)(col + 1 - row0) : -1e30f;
            float s2 = (col     <= row1) ? sacc[j][2] * sc2 + sl2 * (float)(col     - row1) : -1e30f;
            float s3 = (col + 1 <= row1) ? sacc[j][3] * sc2 + sl2 * (float)(col + 1 - row1) : -1e30f;
            sacc[j][0] = s0; sacc[j][1] = s1; sacc[j][2] = s2; sacc[j][3] = s3;
            mx0 = fmaxf(mx0, fmaxf(s0, s1));
            mx1 = fmaxf(mx1, fmaxf(s2, s3));
        }
        mx0 = fmaxf(mx0, __shfl_xor_sync(0xFFFFFFFFu, mx0, 1));
        mx0 = fmaxf(mx0, __shfl_xor_sync(0xFFFFFFFFu, mx0, 2));
        mx1 = fmaxf(mx1, __shfl_xor_sync(0xFFFFFFFFu, mx1, 1));
        mx1 = fmaxf(mx1, __shfl_xor_sync(0xFFFFFFFFu, mx1, 2));
        float mn0 = fmaxf(m0r, mx0), mn1 = fmaxf(m1r, mx1);
        float cr0 = exp2f(m0r - mn0), cr1 = exp2f(m1r - mn1);
        m0r = mn0; m1r = mn1;
        l0 *= cr0; l1 *= cr1;
#pragma unroll
        for (int j = 0; j < 8; j++) {
            float p0 = exp2f(sacc[j][0] - mn0);
            float p1 = exp2f(sacc[j][1] - mn0);
            float p2 = exp2f(sacc[j][2] - mn1);
            float p3 = exp2f(sacc[j][3] - mn1);
            l0 += p0 + p1; l1 += p2 + p3;
            sacc[j][0] = p0; sacc[j][1] = p1; sacc[j][2] = p2; sacc[j][3] = p3;
        }
#pragma unroll
        for (int j = 0; j < 8; j++) {
            oacc[j][0] *= cr0; oacc[j][1] *= cr0;
            oacc[j][2] *= cr1; oacc[j][3] *= cr1;
        }

        // P fragments: RN hi + residual lo (C->A layout recast)
        uint32_t pah[4][4], pal[4][4];
#pragma unroll
        for (int t = 0; t < 4; t++) {
            pah[t][0] = pack_rn_hi2(sacc[2 * t][0],     sacc[2 * t][1]);
            pah[t][1] = pack_rn_hi2(sacc[2 * t][2],     sacc[2 * t][3]);
            pah[t][2] = pack_rn_hi2(sacc[2 * t + 1][0], sacc[2 * t + 1][1]);
            pah[t][3] = pack_rn_hi2(sacc[2 * t + 1][2], sacc[2 * t + 1][3]);
            pal[t][0] = pack_rn_lo2(sacc[2 * t][0],     sacc[2 * t][1],     pah[t][0]);
            pal[t][1] = pack_rn_lo2(sacc[2 * t][2],     sacc[2 * t][3],     pah[t][1]);
            pal[t][2] = pack_rn_lo2(sacc[2 * t + 1][0], sacc[2 * t + 1][1], pah[t][2]);
            pal[t][3] = pack_rn_lo2(sacc[2 * t + 1][2], sacc[2 * t + 1][3], pah[t][3]);
        }

#pragma unroll
        for (int g = 0; g < 4; g++) {
            const int cv = 2 * g + vc8h;
#pragma unroll
            for (int ks = 0; ks < 4; ks++) {
                uint32_t vfh[4], vfl[4];
                const int rowV = 16 * ks + rVl;
                const uint32_t voff = (uint32_t)(cv * 8 + (rowV >> 3)) * 128
                                    + (((rowV & 7) ^ cv) * 16);
                ldm4t(vfh, Vh + voff);
                ldm4t(vfl, Vl + voff);
                mma16816(oacc[2 * g],     pah[ks], vfh);
                mma16816(oacc[2 * g + 1], pah[ks], vfh + 2);
                mma16816(oacc[2 * g],     pah[ks], vfl);
                mma16816(oacc[2 * g + 1], pah[ks], vfl + 2);
                mma16816(oacc[2 * g],     pal[ks], vfh);
                mma16816(oacc[2 * g + 1], pal[ks], vfh + 2);
            }
        }
    }

    l0 += __shfl_xor_sync(0xFFFFFFFFu, l0, 1);
    l0 += __shfl_xor_sync(0xFFFFFFFFu, l0, 2);
    l1 += __shfl_xor_sync(0xFFFFFFFFu, l1, 1);
    l1 += __shfl_xor_sync(0xFFFFFFFFu, l1, 2);
    const float iv0 = 1.0f / l0, iv1 = 1.0f / l1;
    const size_t gr0 = (rbase + row0) * C_;
    const size_t gr1 = (rbase + row1) * C_;
#pragma unroll
    for (int j = 0; j < 8; j++) {
        int col = h * DH_ + j * 8 + (lane & 3) * 2;
        float o0 = oacc[j][0] * iv0, o1 = oacc[j][1] * iv0;
        float o2 = oacc[j][2] * iv1, o3 = oacc[j][3] * iv1;
        uint32_t h0 = pack_rn_hi2(o0, o1), h1 = pack_rn_hi2(o2, o3);
        *(uint32_t*)(oh + gr0 + col) = h0;
        *(uint32_t*)(ol + gr0 + col) = pack_rn_lo2(o0, o1, h0);
        *(uint32_t*)(oh + gr1 + col) = h1;
        *(uint32_t*)(ol + gr1 + col) = pack_rn_lo2(o2, o3, h1);
    }
}

// ---------------------------------------------------------------------------
extern "C" void kernel_launch(void* const* d_in, const int* in_sizes, int n_in,
                              void* d_out, int out_size)
{
    const float* x     = (const float*)d_in[0];
    const float* w_qkv = (const float*)d_in[1];
    const float* w_o   = (const float*)d_in[2];
    float* out = (float*)d_out;

    __nv_bfloat16 *xhi, *xlo, *qkvh, *qkvl, *wqhi, *wqlo, *wohi, *wolo;
    cudaGetSymbolAddress((void**)&xhi,  g_xhi);
    cudaGetSymbolAddress((void**)&xlo,  g_xlo);
    cudaGetSymbolAddress((void**)&qkvh, g_qkvh);
    cudaGetSymbolAddress((void**)&qkvl, g_qkvl);
    cudaGetSymbolAddress((void**)&wqhi, g_wqhi);
    cudaGetSymbolAddress((void**)&wqlo, g_wqlo);
    cudaGetSymbolAddress((void**)&wohi, g_wohi);
    cudaGetSymbolAddress((void**)&wolo, g_wolo);

    cudaFuncSetAttribute(gemm_mma, cudaFuncAttributeMaxDynamicSharedMemorySize, GEMM_SMEM);
    cudaFuncSetAttribute(attn_mma, cudaFuncAttributeMaxDynamicSharedMemorySize, ATT_SMEM);

    split_f32<<<(M_ * C_ + 255) / 256, 256>>>(x, xhi, xlo, M_ * C_);
    splitT_f32<<<dim3(C3_ / 32, C_ / 32), dim3(32, 8)>>>(w_qkv, wqhi, wqlo, C_, C3_);
    splitT_f32<<<dim3(C_ / 32,  C_ / 32), dim3(32, 8)>>>(w_o,   wohi, wolo, C_, C_);

    // 1a) Q,K columns [0,2048): 2-product (scores tolerate ~1e-3 operand error)
    gemm_mma<<<dim3(2048 / 128, M_ / 128), 256, GEMM_SMEM>>>(
        xhi, xlo, wqhi, wqlo, nullptr, qkvh, qkvl, C3_, 2);
    // 1b) V columns [2048,3072): full 3-product
    gemm_mma<<<dim3(1024 / 128, M_ / 128), 256, GEMM_SMEM>>>(
        xhi, xlo, wqhi + (size_t)2048 * K_, wqlo + (size_t)2048 * K_,
        nullptr, qkvh + 2048, qkvl + 2048, C3_, 3);

    // 2) flash attention (QK 2-product, PV 3-product)
    attn_mma<<<dim3(T_ / AQT, H_, B_), 256, ATT_SMEM>>>(qkvh, qkvl, xhi, xlo);

    // 3) out = attn @ w_o (3-product, fp32 out)
    gemm_mma<<<dim3(C_ / 128, M_ / 128), 256, GEMM_SMEM>>>(
        xhi, xlo, wohi, wolo, out, nullptr, nullptr, C_, 3);
}

// round 10
// speedup vs baseline: 1.8036x; 1.5116x over previous
#include <cuda_runtime.h>
#include <cuda_fp16.h>
#include <cstdint>

#define B_   4
#define T_   2048
#define C_   1024
#define H_   16
#define DH_  64
#define C3_  3072
#define M_   (B_*T_)      // 8192 rows
#define K_   1024

// ---------------------------------------------------------------------------
// Scratch (no cudaMalloc). g_xh reused for attention fp16 output (x dead by then).
// ---------------------------------------------------------------------------
__device__ __half g_xh[(size_t)M_ * C_];
__device__ __half g_qkvh[(size_t)M_ * C3_];   // Q,K,V hi (fp16)
__device__ __half g_qkvl[(size_t)M_ * C3_];   // only V region (cols 2048+) used
__device__ __half g_wqh[(size_t)C3_ * C_];    // W_qkv^T fp16
__device__ __half g_wql[(size_t)C3_ * C_];    // residual (only V rows used)
__device__ __half g_woh[(size_t)C_ * C_];     // W_o^T fp16 hi
__device__ __half g_wol[(size_t)C_ * C_];     // W_o^T residual

// ---------------------------------------------------------------------------
__device__ __forceinline__ uint32_t smem_u32(const void* p) {
    uint32_t a;
    asm("{ .reg .u64 t; cvta.to.shared.u64 t, %1; cvt.u32.u64 %0, t; }" : "=r"(a) : "l"(p));
    return a;
}
__device__ __forceinline__ void cpa16(uint32_t dst, const void* src) {
    asm volatile("cp.async.cg.shared.global [%0], [%1], 16;" :: "r"(dst), "l"(src));
}
__device__ __forceinline__ void ldm4(uint32_t* r, uint32_t addr) {
    asm volatile("ldmatrix.sync.aligned.m8n8.x4.shared.b16 {%0,%1,%2,%3}, [%4];"
                 : "=r"(r[0]), "=r"(r[1]), "=r"(r[2]), "=r"(r[3]) : "r"(addr));
}
__device__ __forceinline__ void ldm4t(uint32_t* r, uint32_t addr) {
    asm volatile("ldmatrix.sync.aligned.m8n8.x4.trans.shared.b16 {%0,%1,%2,%3}, [%4];"
                 : "=r"(r[0]), "=r"(r[1]), "=r"(r[2]), "=r"(r[3]) : "r"(addr));
}
// fp16 mma, fp32 accumulate
__device__ __forceinline__ void mma16816h(float* d, const uint32_t* a, const uint32_t* b) {
    asm volatile("mma.sync.aligned.m16n8k16.row.col.f32.f16.f16.f32 "
                 "{%0,%1,%2,%3}, {%4,%5,%6,%7}, {%8,%9}, {%0,%1,%2,%3};"
                 : "+f"(d[0]), "+f"(d[1]), "+f"(d[2]), "+f"(d[3])
                 : "r"(a[0]), "r"(a[1]), "r"(a[2]), "r"(a[3]), "r"(b[0]), "r"(b[1]));
}
// fp16x2 pack, a in low half
__device__ __forceinline__ uint32_t pack_h2(float a, float b) {
    uint32_t r;
    asm("cvt.rn.f16x2.f32 %0, %1, %2;" : "=r"(r) : "f"(b), "f"(a));
    return r;
}
// residual pair against a pack
__device__ __forceinline__ uint32_t pack_h2_lo(float a, float b, uint32_t hi) {
    __half2 h = *reinterpret_cast<__half2*>(&hi);
    float2 f = __half22float2(h);
    return pack_h2(a - f.x, b - f.y);
}

// ---------------------------------------------------------------------------
__global__ void to_h16(const float* __restrict__ x, __half* __restrict__ o, int n)
{
    int i = blockIdx.x * blockDim.x + threadIdx.x;
    if (i < n) o[i] = __float2half_rn(x[i]);
}

// Transpose + split: W[K][N] fp32 -> Thi/Tlo[N][K] fp16
__global__ void splitT_h16(const float* __restrict__ W,
                           __half* __restrict__ Thi,
                           __half* __restrict__ Tlo, int K, int N)
{
    __shared__ float t[32][33];
    int n0 = blockIdx.x * 32, k0 = blockIdx.y * 32;
    int tx = threadIdx.x, ty = threadIdx.y;
    for (int r = ty; r < 32; r += 8)
        t[r][tx] = W[(size_t)(k0 + r) * N + n0 + tx];
    __syncthreads();
    for (int r = ty; r < 32; r += 8) {
        float v = t[tx][r];
        __half h = __float2half_rn(v);
        size_t o = (size_t)(n0 + r) * K + k0 + tx;
        Thi[o] = h;
        Tlo[o] = __float2half_rn(v - __half2float(h));
    }
}

// ---------------------------------------------------------------------------
// mma.sync fp16 GEMM:  C[M,N] = A[M,K] * B^T.  A single fp16.
// nprod==1: A*Bh.  nprod==2: A*Bh + A*Bl (B stored as hi/lo residual pair).
// CTA 128x128, BK=32, 3-stage cp.async, XOR-swizzled smem, 2 CTAs/SM.
// ---------------------------------------------------------------------------
#define BKSLAB     32
#define OPB        8192
#define STAGEB     (3 * OPB)            // A, Bh, Bl
#define GSTAGES    3
#define GEMM_SMEM  (GSTAGES * STAGEB)   // 73728 B

__global__ void __launch_bounds__(256, 2) gemm_mma(
    const __half* __restrict__ Ah_, const __half* __restrict__ Bh_,
    const __half* __restrict__ Bl_,
    float* __restrict__ Cf, __half* __restrict__ Chi,
    __half* __restrict__ Clo, int N, int nprod)
{
    extern __shared__ char smem[];
    const uint32_t sb = smem_u32(smem);
    const int tid  = threadIdx.x;
    const int m0   = blockIdx.y * 128;
    const int n0   = blockIdx.x * 128;
    const int wid  = tid >> 5, lane = tid & 31;
    const int warp_m = (wid & 1) * 64;
    const int warp_n = (wid >> 1) * 32;

    const __half* pA  = Ah_ + (size_t)m0 * K_;
    const __half* pBh = Bh_ + (size_t)n0 * K_;
    const __half* pBl = Bl_ ? Bl_ + (size_t)n0 * K_ : nullptr;

    auto load_stage = [&](int it, int slot) {
        const uint32_t st = sb + slot * STAGEB;
        const int kb = it * BKSLAB;
#pragma unroll
        for (int i = 0; i < 6; i++) {
            if (i >= 4 && nprod < 2) continue;       // Bl unused
            const __half* base = (i < 2) ? pA : (i < 4) ? pBh : pBl;
            int w   = ((i & 1) << 8) + tid;
            int row = w >> 2;
            int c   = w & 3;
            const void* src = base + (size_t)row * K_ + kb + c * 8;
            uint32_t dst = st + (i >> 1) * OPB + (c * 16 + (row >> 3)) * 128
                         + (((row & 7) ^ (c << 1)) * 16);
            cpa16(dst, src);
        }
        asm volatile("cp.async.commit_group;" ::: "memory");
    };

    float acc[4][4][4];
#pragma unroll
    for (int a = 0; a < 4; a++)
#pragma unroll
        for (int b = 0; b < 4; b++)
#pragma unroll
            for (int c = 0; c < 4; c++) acc[a][b][c] = 0.f;

    const int mA  = warp_m + (lane & 15);
    const int mA8 = mA >> 3, mA7 = mA & 7;
    const int k8A = lane >> 4;
    const int nB  = warp_n + ((lane >> 4) << 3) + (lane & 7);
    const int nB8 = nB >> 3, nB7 = nB & 7;
    const int k8B = (lane >> 3) & 1;

    load_stage(0, 0);
    load_stage(1, 1);

    const int NIT = K_ / BKSLAB;
    for (int it = 0; it < NIT; it++) {
        if (it + 1 < NIT) asm volatile("cp.async.wait_group 1;" ::: "memory");
        else              asm volatile("cp.async.wait_group 0;" ::: "memory");
        __syncthreads();
        if (it + 2 < NIT) load_stage(it + 2, (it + 2) % GSTAGES);

        const uint32_t st = sb + (it % GSTAGES) * STAGEB;
        const uint32_t AH = st, BH = st + OPB, BL = st + 2 * OPB;

#pragma unroll
        for (int ks = 0; ks < 2; ks++) {
            const int cA = ks * 2 + k8A;
            const int cB = ks * 2 + k8B;
            const uint32_t offA = (uint32_t)(cA * 16 + mA8) * 128 + ((mA7 ^ (cA << 1)) * 16);
            const uint32_t offB = (uint32_t)(cB * 16 + nB8) * 128 + ((nB7 ^ (cB << 1)) * 16);

            uint32_t ah[4][4], bb[4][2];
#pragma unroll
            for (int mt = 0; mt < 4; mt++)
                ldm4(ah[mt], AH + offA + mt * 256);
#pragma unroll
            for (int j = 0; j < 2; j++)
                ldm4(&bb[j * 2][0], BH + offB + j * 256);
#pragma unroll
            for (int mt = 0; mt < 4; mt++)
#pragma unroll
                for (int nt = 0; nt < 4; nt++) mma16816h(acc[mt][nt], ah[mt], bb[nt]);
            if (nprod == 2) {
#pragma unroll
                for (int j = 0; j < 2; j++)
                    ldm4(&bb[j * 2][0], BL + offB + j * 256);
#pragma unroll
                for (int mt = 0; mt < 4; mt++)
#pragma unroll
                    for (int nt = 0; nt < 4; nt++) mma16816h(acc[mt][nt], ah[mt], bb[nt]);
            }
        }
    }

    const int r0 = m0 + warp_m + (lane >> 2);
    const int c0 = n0 + warp_n + (lane & 3) * 2;
    if (Chi) {
#pragma unroll
        for (int mt = 0; mt < 4; mt++) {
#pragma unroll
            for (int nt = 0; nt < 4; nt++) {
                size_t o0 = (size_t)(r0 + mt * 16) * N + c0 + nt * 8;
                size_t o1 = o0 + (size_t)8 * N;
                uint32_t h0 = pack_h2(acc[mt][nt][0], acc[mt][nt][1]);
                uint32_t h1 = pack_h2(acc[mt][nt][2], acc[mt][nt][3]);
                *(uint32_t*)(Chi + o0) = h0;
                *(uint32_t*)(Chi + o1) = h1;
                if (Clo) {
                    *(uint32_t*)(Clo + o0) = pack_h2_lo(acc[mt][nt][0], acc[mt][nt][1], h0);
                    *(uint32_t*)(Clo + o1) = pack_h2_lo(acc[mt][nt][2], acc[mt][nt][3], h1);
                }
            }
        }
    } else {
#pragma unroll
        for (int mt = 0; mt < 4; mt++) {
#pragma unroll
            for (int nt = 0; nt < 4; nt++) {
                float* p = Cf + (size_t)(r0 + mt * 16) * N + c0 + nt * 8;
                *(float2*)p                   = make_float2(acc[mt][nt][0], acc[mt][nt][1]);
                *(float2*)(p + (size_t)8 * N) = make_float2(acc[mt][nt][2], acc[mt][nt][3]);
            }
        }
    }
}

// ---------------------------------------------------------------------------
// fp16 flash attention, causal + ALiBi.
// QK^T: single product (Q,K single fp16).  PV: P single x V hi/lo pair.
// ---------------------------------------------------------------------------
#define AQT       128
#define AKT       64
#define AOPB      8192
#define ASTAGEB   (3 * AOPB)             // Kh, Vh, Vl
#define ATT_SMEM  (16384 + 2 * ASTAGEB)  // 65536 B

__global__ void __launch_bounds__(256, 2) attn_mma(
    const __half* __restrict__ qkvh, const __half* __restrict__ qkvl,
    __half* __restrict__ oh)
{
    extern __shared__ char smem[];
    const uint32_t sb = smem_u32(smem);
    const uint32_t Qh = sb;
    const uint32_t ST0 = sb + 16384;

    const int tid  = threadIdx.x;
    const int wid  = tid >> 5, lane = tid & 31;
    const int b    = blockIdx.z;
    const int h    = blockIdx.y;
    const int qt   = blockIdx.x;
    const int q0   = qt * AQT;
    const int nkt  = 2 * qt + 2;
    const size_t rbase = (size_t)b * T_;

    const float LOG2E = 1.4426950408889634f;
    const float sc2 = LOG2E / 32.0f;
    const float sl2 = exp2f(-0.5f * (float)(h + 1)) * LOG2E;

    // Q tile (single fp16): 128 x 64 x 2B = 1024 chunks
    for (int i = tid; i < 1024; i += 256) {
        int r = (i >> 3) & 127, c8 = i & 7;
        const void* src = qkvh + (rbase + q0 + r) * C3_ + h * DH_ + c8 * 8;
        uint32_t dst = Qh + (c8 * 16 + (r >> 3)) * 128 + (((r & 7) ^ c8) * 16);
        cpa16(dst, src);
    }
    auto load_stage = [&](int kt, int slot) {
        const int k0 = kt * AKT;
        const uint32_t st = ST0 + slot * ASTAGEB;
        for (int i = tid; i < 1536; i += 256) {
            int op = i >> 9, r = (i >> 3) & 63, c8 = i & 7;
            const __half* g = (op == 2) ? qkvl : qkvh;
            int coloff = ((op == 0) ? C_ : 2 * C_) + h * DH_;
            const void* src = g + (rbase + k0 + r) * C3_ + coloff + c8 * 8;
            uint32_t dst = st + op * AOPB + (c8 * 8 + (r >> 3)) * 128 + (((r & 7) ^ c8) * 16);
            cpa16(dst, src);
        }
        asm volatile("cp.async.commit_group;" ::: "memory");
    };
    load_stage(0, 0);

    float oacc[8][4];
#pragma unroll
    for (int j = 0; j < 8; j++)
#pragma unroll
        for (int c = 0; c < 4; c++) oacc[j][c] = 0.f;
    float m0r = -1e30f, m1r = -1e30f, l0 = 0.f, l1 = 0.f;

    const int rA   = wid * 16 + (lane & 15);
    const int rA8  = rA >> 3, rA7 = rA & 7;
    const int qc8h = lane >> 4;
    const int nKl  = (lane & 7) + ((lane >> 4) << 3);
    const int kc8h = (lane >> 3) & 1;
    const int rVl  = (lane & 7) + (((lane >> 3) & 1) << 3);
    const int vc8h = lane >> 4;
    const int row0 = q0 + wid * 16 + (lane >> 2);
    const int row1 = row0 + 8;

    for (int kt = 0; kt < nkt; kt++) {
        asm volatile("cp.async.wait_group 0;" ::: "memory");
        __syncthreads();
        if (kt + 1 < nkt) load_stage(kt + 1, (kt + 1) & 1);

        const int k0 = kt * AKT;
        const uint32_t st = ST0 + (kt & 1) * ASTAGEB;
        const uint32_t Kh = st, Vh = st + AOPB, Vl = st + 2 * AOPB;

        float sacc[8][4];
#pragma unroll
        for (int j = 0; j < 8; j++)
#pragma unroll
            for (int c = 0; c < 4; c++) sacc[j][c] = 0.f;

#pragma unroll
        for (int ks = 0; ks < 4; ks++) {
            const int cq = 2 * ks + qc8h;
            const int ck = 2 * ks + kc8h;
            uint32_t qfh[4];
            const uint32_t qoff = (uint32_t)(cq * 16 + rA8) * 128 + ((rA7 ^ cq) * 16);
            ldm4(qfh, Qh + qoff);
#pragma unroll
            for (int j = 0; j < 4; j++) {
                uint32_t kfh[4];
                const int rowK = 16 * j + nKl;
                const uint32_t koff = (uint32_t)(ck * 8 + (rowK >> 3)) * 128
                                    + (((rowK & 7) ^ ck) * 16);
                ldm4(kfh, Kh + koff);
                mma16816h(sacc[2 * j],     qfh, kfh);
                mma16816h(sacc[2 * j + 1], qfh, kfh + 2);
            }
        }

        float mx0 = -1e30f, mx1 = -1e30f;
#pragma unroll
        for (int j = 0; j < 8; j++) {
            int col = k0 + j * 8 + (lane & 3) * 2;
            float s0 = (col     <= row0) ? sacc[j][0] * sc2 + sl2 * (float)(col     - row0) : -1e30f;
            float s1 = (col + 1 <= row0) ? sacc[j][1] * sc2 + sl2 * (float)(col + 1 - row0) : -1e30f;
            float s2 = (col     <= row1) ? sacc[j][2] * sc2 + sl2 * (float)(col     - row1) : -1e30f;
            float s3 = (col + 1 <= row1) ? sacc[j][3] * sc2 + sl2 * (float)(col + 1 - row1) : -1e30f;
            sacc[j][0] = s0; sacc[j][1] = s1; sacc[j][2] = s2; sacc[j][3] = s3;
            mx0 = fmaxf(mx0, fmaxf(s0, s1));
            mx1 = fmaxf(mx1, fmaxf(s2, s3));
        }
        mx0 = fmaxf(mx0, __shfl_xor_sync(0xFFFFFFFFu, mx0, 1));
        mx0 = fmaxf(mx0, __shfl_xor_sync(0xFFFFFFFFu, mx0, 2));
        mx1 = fmaxf(mx1, __shfl_xor_sync(0xFFFFFFFFu, mx1, 1));
        mx1 = fmaxf(mx1, __shfl_xor_sync(0xFFFFFFFFu, mx1, 2));
        float mn0 = fmaxf(m0r, mx0), mn1 = fmaxf(m1r, mx1);
        float cr0 = exp2f(m0r - mn0), cr1 = exp2f(m1r - mn1);
        m0r = mn0; m1r = mn1;
        l0 *= cr0; l1 *= cr1;
#pragma unroll
        for (int j = 0; j < 8; j++) {
            float p0 = exp2f(sacc[j][0] - mn0);
            float p1 = exp2f(sacc[j][1] - mn0);
            float p2 = exp2f(sacc[j][2] - mn1);
            float p3 = exp2f(sacc[j][3] - mn1);
            l0 += p0 + p1; l1 += p2 + p3;
            sacc[j][0] = p0; sacc[j][1] = p1; sacc[j][2] = p2; sacc[j][3] = p3;
        }
#pragma unroll
        for (int j = 0; j < 8; j++) {
            oacc[j][0] *= cr0; oacc[j][1] *= cr0;
            oacc[j][2] *= cr1; oacc[j][3] *= cr1;
        }

        // P fragments (single fp16)
        uint32_t pah[4][4];
#pragma unroll
        for (int t = 0; t < 4; t++) {
            pah[t][0] = pack_h2(sacc[2 * t][0],     sacc[2 * t][1]);
            pah[t][1] = pack_h2(sacc[2 * t][2],     sacc[2 * t][3]);
            pah[t][2] = pack_h2(sacc[2 * t + 1][0], sacc[2 * t + 1][1]);
            pah[t][3] = pack_h2(sacc[2 * t + 1][2], sacc[2 * t + 1][3]);
        }

#pragma unroll
        for (int g = 0; g < 4; g++) {
            const int cv = 2 * g + vc8h;
#pragma unroll
            for (int ks = 0; ks < 4; ks++) {
                uint32_t vfh[4], vfl[4];
                const int rowV = 16 * ks + rVl;
                const uint32_t voff = (uint32_t)(cv * 8 + (rowV >> 3)) * 128
                                    + (((rowV & 7) ^ cv) * 16);
                ldm4t(vfh, Vh + voff);
                ldm4t(vfl, Vl + voff);
                mma16816h(oacc[2 * g],     pah[ks], vfh);
                mma16816h(oacc[2 * g + 1], pah[ks], vfh + 2);
                mma16816h(oacc[2 * g],     pah[ks], vfl);
                mma16816h(oacc[2 * g + 1], pah[ks], vfl + 2);
            }
        }
    }

    l0 += __shfl_xor_sync(0xFFFFFFFFu, l0, 1);
    l0 += __shfl_xor_sync(0xFFFFFFFFu, l0, 2);
    l1 += __shfl_xor_sync(0xFFFFFFFFu, l1, 1);
    l1 += __shfl_xor_sync(0xFFFFFFFFu, l1, 2);
    const float iv0 = 1.0f / l0, iv1 = 1.0f / l1;
    const size_t gr0 = (rbase + row0) * C_;
    const size_t gr1 = (rbase + row1) * C_;
#pragma unroll
    for (int j = 0; j < 8; j++) {
        int col = h * DH_ + j * 8 + (lane & 3) * 2;
        *(uint32_t*)(oh + gr0 + col) = pack_h2(oacc[j][0] * iv0, oacc[j][1] * iv0);
        *(uint32_t*)(oh + gr1 + col) = pack_h2(oacc[j][2] * iv1, oacc[j][3] * iv1);
    }
}

// ---------------------------------------------------------------------------
extern "C" void kernel_launch(void* const* d_in, const int* in_sizes, int n_in,
                              void* d_out, int out_size)
{
    const float* x     = (const float*)d_in[0];
    const float* w_qkv = (const float*)d_in[1];
    const float* w_o   = (const float*)d_in[2];
    float* out = (float*)d_out;

    __half *xh, *qkvh, *qkvl, *wqh, *wql, *woh, *wol;
    cudaGetSymbolAddress((void**)&xh,   g_xh);
    cudaGetSymbolAddress((void**)&qkvh, g_qkvh);
    cudaGetSymbolAddress((void**)&qkvl, g_qkvl);
    cudaGetSymbolAddress((void**)&wqh,  g_wqh);
    cudaGetSymbolAddress((void**)&wql,  g_wql);
    cudaGetSymbolAddress((void**)&woh,  g_woh);
    cudaGetSymbolAddress((void**)&wol,  g_wol);

    cudaFuncSetAttribute(gemm_mma, cudaFuncAttributeMaxDynamicSharedMemorySize, GEMM_SMEM);
    cudaFuncSetAttribute(attn_mma, cudaFuncAttributeMaxDynamicSharedMemorySize, ATT_SMEM);

    // 0) input / weight conversion
    to_h16<<<(M_ * C_ + 255) / 256, 256>>>(x, xh, M_ * C_);
    splitT_h16<<<dim3(C3_ / 32, C_ / 32), dim3(32, 8)>>>(w_qkv, wqh, wql, C_, C3_);
    splitT_h16<<<dim3(C_ / 32,  C_ / 32), dim3(32, 8)>>>(w_o,   woh, wol, C_, C_);

    // 1a) Q,K: single product (both roundings softmax-dampened)
    gemm_mma<<<dim3(2048 / 128, M_ / 128), 256, GEMM_SMEM>>>(
        xh, wqh, nullptr, nullptr, qkvh, nullptr, C3_, 1);
    // 1b) V: 2 products (W residual kept; V stored as hi/lo pair)
    gemm_mma<<<dim3(1024 / 128, M_ / 128), 256, GEMM_SMEM>>>(
        xh, wqh + (size_t)2048 * K_, wql + (size_t)2048 * K_,
        nullptr, qkvh + 2048, qkvl + 2048, C3_, 2);

    // 2) flash attention (QK single product, PV 2 products); O -> xh (fp16)
    attn_mma<<<dim3(T_ / AQT, H_, B_), 256, ATT_SMEM>>>(qkvh, qkvl, xh);

    // 3) out = O @ w_o (2 products, fp32 out)
    gemm_mma<<<dim3(C_ / 128, M_ / 128), 256, GEMM_SMEM>>>(
        xh, woh, wol, out, nullptr, nullptr, C_, 2);
}

// round 12
// speedup vs baseline: 2.3878x; 1.3239x over previous
#include <cuda_runtime.h>
#include <cuda_fp16.h>
#include <cstdint>

#define B_   4
#define T_   2048
#define C_   1024
#define H_   16
#define DH_  64
#define C3_  3072
#define M_   (B_*T_)      // 8192 rows
#define K_   1024

// ---------------------------------------------------------------------------
// Scratch (no cudaMalloc). g_xh reused for attention fp16 output (x dead by then).
// ---------------------------------------------------------------------------
__device__ __half g_xh[(size_t)M_ * C_];
__device__ __half g_qkvh[(size_t)M_ * C3_];   // Q,K,V (fp16, single)
__device__ __half g_wqh[(size_t)C3_ * C_];    // W_qkv^T fp16
__device__ __half g_woh[(size_t)C_ * C_];     // W_o^T fp16

// ---------------------------------------------------------------------------
__device__ __forceinline__ uint32_t smem_u32(const void* p) {
    uint32_t a;
    asm("{ .reg .u64 t; cvta.to.shared.u64 t, %1; cvt.u32.u64 %0, t; }" : "=r"(a) : "l"(p));
    return a;
}
__device__ __forceinline__ void cpa16(uint32_t dst, const void* src) {
    asm volatile("cp.async.cg.shared.global [%0], [%1], 16;" :: "r"(dst), "l"(src));
}
__device__ __forceinline__ void ldm4(uint32_t* r, uint32_t addr) {
    asm volatile("ldmatrix.sync.aligned.m8n8.x4.shared.b16 {%0,%1,%2,%3}, [%4];"
                 : "=r"(r[0]), "=r"(r[1]), "=r"(r[2]), "=r"(r[3]) : "r"(addr));
}
__device__ __forceinline__ void ldm4t(uint32_t* r, uint32_t addr) {
    asm volatile("ldmatrix.sync.aligned.m8n8.x4.trans.shared.b16 {%0,%1,%2,%3}, [%4];"
                 : "=r"(r[0]), "=r"(r[1]), "=r"(r[2]), "=r"(r[3]) : "r"(addr));
}
__device__ __forceinline__ void mma16816h(float* d, const uint32_t* a, const uint32_t* b) {
    asm volatile("mma.sync.aligned.m16n8k16.row.col.f32.f16.f16.f32 "
                 "{%0,%1,%2,%3}, {%4,%5,%6,%7}, {%8,%9}, {%0,%1,%2,%3};"
                 : "+f"(d[0]), "+f"(d[1]), "+f"(d[2]), "+f"(d[3])
                 : "r"(a[0]), "r"(a[1]), "r"(a[2]), "r"(a[3]), "r"(b[0]), "r"(b[1]));
}
__device__ __forceinline__ uint32_t pack_h2(float a, float b) {
    uint32_t r;
    asm("cvt.rn.f16x2.f32 %0, %1, %2;" : "=r"(r) : "f"(b), "f"(a));
    return r;
}

// ---------------------------------------------------------------------------
__global__ void to_h16(const float* __restrict__ x, __half* __restrict__ o, int n)
{
    int i = blockIdx.x * blockDim.x + threadIdx.x;
    if (i < n) o[i] = __float2half_rn(x[i]);
}

// Transpose: W[K][N] fp32 -> T[N][K] fp16
__global__ void transT_h16(const float* __restrict__ W,
                           __half* __restrict__ Th, int K, int N)
{
    __shared__ float t[32][33];
    int n0 = blockIdx.x * 32, k0 = blockIdx.y * 32;
    int tx = threadIdx.x, ty = threadIdx.y;
    for (int r = ty; r < 32; r += 8)
        t[r][tx] = W[(size_t)(k0 + r) * N + n0 + tx];
    __syncthreads();
    for (int r = ty; r < 32; r += 8)
        Th[(size_t)(n0 + r) * K + k0 + tx] = __float2half_rn(t[tx][r]);
}

// ---------------------------------------------------------------------------
// mma.sync fp16 GEMM:  C[M,N] = A[M,K] * B^T, single product.
// CTA 128x128, BK=32, 3-stage cp.async, XOR-swizzled smem.
// ---------------------------------------------------------------------------
#define BKSLAB     32
#define OPB        8192
#define STAGEB     (2 * OPB)            // A, B
#define GSTAGES    3
#define GEMM_SMEM  (GSTAGES * STAGEB)   // 49152 B

__global__ void __launch_bounds__(256, 2) gemm_mma(
    const __half* __restrict__ Ah_, const __half* __restrict__ Bh_,
    float* __restrict__ Cf, __half* __restrict__ Chi, int N)
{
    extern __shared__ char smem[];
    const uint32_t sb = smem_u32(smem);
    const int tid  = threadIdx.x;
    const int m0   = blockIdx.y * 128;
    const int n0   = blockIdx.x * 128;
    const int wid  = tid >> 5, lane = tid & 31;
    const int warp_m = (wid & 1) * 64;
    const int warp_n = (wid >> 1) * 32;

    const __half* pA  = Ah_ + (size_t)m0 * K_;
    const __half* pBh = Bh_ + (size_t)n0 * K_;

    auto load_stage = [&](int it, int slot) {
        const uint32_t st = sb + slot * STAGEB;
        const int kb = it * BKSLAB;
#pragma unroll
        for (int i = 0; i < 4; i++) {
            const __half* base = (i < 2) ? pA : pBh;
            int w   = ((i & 1) << 8) + tid;
            int row = w >> 2;
            int c   = w & 3;
            const void* src = base + (size_t)row * K_ + kb + c * 8;
            uint32_t dst = st + (i >> 1) * OPB + (c * 16 + (row >> 3)) * 128
                         + (((row & 7) ^ (c << 1)) * 16);
            cpa16(dst, src);
        }
        asm volatile("cp.async.commit_group;" ::: "memory");
    };

    float acc[4][4][4];
#pragma unroll
    for (int a = 0; a < 4; a++)
#pragma unroll
        for (int b = 0; b < 4; b++)
#pragma unroll
            for (int c = 0; c < 4; c++) acc[a][b][c] = 0.f;

    const int mA  = warp_m + (lane & 15);
    const int mA8 = mA >> 3, mA7 = mA & 7;
    const int k8A = lane >> 4;
    const int nB  = warp_n + ((lane >> 4) << 3) + (lane & 7);
    const int nB8 = nB >> 3, nB7 = nB & 7;
    const int k8B = (lane >> 3) & 1;

    load_stage(0, 0);
    load_stage(1, 1);

    const int NIT = K_ / BKSLAB;
    for (int it = 0; it < NIT; it++) {
        if (it + 1 < NIT) asm volatile("cp.async.wait_group 1;" ::: "memory");
        else              asm volatile("cp.async.wait_group 0;" ::: "memory");
        __syncthreads();
        if (it + 2 < NIT) load_stage(it + 2, (it + 2) % GSTAGES);

        const uint32_t st = sb + (it % GSTAGES) * STAGEB;
        const uint32_t AH = st, BH = st + OPB;

#pragma unroll
        for (int ks = 0; ks < 2; ks++) {
            const int cA = ks * 2 + k8A;
            const int cB = ks * 2 + k8B;
            const uint32_t offA = (uint32_t)(cA * 16 + mA8) * 128 + ((mA7 ^ (cA << 1)) * 16);
            const uint32_t offB = (uint32_t)(cB * 16 + nB8) * 128 + ((nB7 ^ (cB << 1)) * 16);

            uint32_t ah[4][4], bb[4][2];
#pragma unroll
            for (int mt = 0; mt < 4; mt++)
                ldm4(ah[mt], AH + offA + mt * 256);
#pragma unroll
            for (int j = 0; j < 2; j++)
                ldm4(&bb[j * 2][0], BH + offB + j * 256);
#pragma unroll
            for (int mt = 0; mt < 4; mt++)
#pragma unroll
                for (int nt = 0; nt < 4; nt++) mma16816h(acc[mt][nt], ah[mt], bb[nt]);
        }
    }

    const int r0 = m0 + warp_m + (lane >> 2);
    const int c0 = n0 + warp_n + (lane & 3) * 2;
    if (Chi) {
#pragma unroll
        for (int mt = 0; mt < 4; mt++) {
#pragma unroll
            for (int nt = 0; nt < 4; nt++) {
                size_t o0 = (size_t)(r0 + mt * 16) * N + c0 + nt * 8;
                size_t o1 = o0 + (size_t)8 * N;
                *(uint32_t*)(Chi + o0) = pack_h2(acc[mt][nt][0], acc[mt][nt][1]);
                *(uint32_t*)(Chi + o1) = pack_h2(acc[mt][nt][2], acc[mt][nt][3]);
            }
        }
    } else {
#pragma unroll
        for (int mt = 0; mt < 4; mt++) {
#pragma unroll
            for (int nt = 0; nt < 4; nt++) {
                float* p = Cf + (size_t)(r0 + mt * 16) * N + c0 + nt * 8;
                *(float2*)p                   = make_float2(acc[mt][nt][0], acc[mt][nt][1]);
                *(float2*)(p + (size_t)8 * N) = make_float2(acc[mt][nt][2], acc[mt][nt][3]);
            }
        }
    }
}

// ---------------------------------------------------------------------------
// fp16 flash attention, causal + ALiBi. All matmuls single product.
// ---------------------------------------------------------------------------
#define AQT       128
#define AKT       64
#define AOPB      8192
#define ASTAGEB   (2 * AOPB)             // K, V
#define ATT_SMEM  (16384 + 2 * ASTAGEB)  // 49152 B

__global__ void __launch_bounds__(256, 2) attn_mma(
    const __half* __restrict__ qkv, __half* __restrict__ oh)
{
    extern __shared__ char smem[];
    const uint32_t sb = smem_u32(smem);
    const uint32_t Qs = sb;
    const uint32_t ST0 = sb + 16384;

    const int tid  = threadIdx.x;
    const int wid  = tid >> 5, lane = tid & 31;
    const int b    = blockIdx.z;
    const int h    = blockIdx.y;
    const int qt   = blockIdx.x;
    const int q0   = qt * AQT;
    const int nkt  = 2 * qt + 2;
    const size_t rbase = (size_t)b * T_;

    const float LOG2E = 1.4426950408889634f;
    const float sc2 = LOG2E / 32.0f;
    const float sl2 = exp2f(-0.5f * (float)(h + 1)) * LOG2E;

    for (int i = tid; i < 1024; i += 256) {
        int r = (i >> 3) & 127, c8 = i & 7;
        const void* src = qkv + (rbase + q0 + r) * C3_ + h * DH_ + c8 * 8;
        uint32_t dst = Qs + (c8 * 16 + (r >> 3)) * 128 + (((r & 7) ^ c8) * 16);
        cpa16(dst, src);
    }
    auto load_stage = [&](int kt, int slot) {
        const int k0 = kt * AKT;
        const uint32_t st = ST0 + slot * ASTAGEB;
        for (int i = tid; i < 1024; i += 256) {
            int op = i >> 9, r = (i >> 3) & 63, c8 = i & 7;
            int coloff = ((op == 0) ? C_ : 2 * C_) + h * DH_;
            const void* src = qkv + (rbase + k0 + r) * C3_ + coloff + c8 * 8;
            uint32_t dst = st + op * AOPB + (c8 * 8 + (r >> 3)) * 128 + (((r & 7) ^ c8) * 16);
            cpa16(dst, src);
        }
        asm volatile("cp.async.commit_group;" ::: "memory");
    };
    load_stage(0, 0);

    float oacc[8][4];
#pragma unroll
    for (int j = 0; j < 8; j++)
#pragma unroll
        for (int c = 0; c < 4; c++) oacc[j][c] = 0.f;
    float m0r = -1e30f, m1r = -1e30f, l0 = 0.f, l1 = 0.f;

    const int rA   = wid * 16 + (lane & 15);
    const int rA8  = rA >> 3, rA7 = rA & 7;
    const int qc8h = lane >> 4;
    const int nKl  = (lane & 7) + ((lane >> 4) << 3);
    const int kc8h = (lane >> 3) & 1;
    const int rVl  = (lane & 7) + (((lane >> 3) & 1) << 3);
    const int vc8h = lane >> 4;
    const int row0 = q0 + wid * 16 + (lane >> 2);
    const int row1 = row0 + 8;

    for (int kt = 0; kt < nkt; kt++) {
        asm volatile("cp.async.wait_group 0;" ::: "memory");
        __syncthreads();
        if (kt + 1 < nkt) load_stage(kt + 1, (kt + 1) & 1);

        const int k0 = kt * AKT;
        const uint32_t st = ST0 + (kt & 1) * ASTAGEB;
        const uint32_t Ks = st, Vs = st + AOPB;

        float sacc[8][4];
#pragma unroll
        for (int j = 0; j < 8; j++)
#pragma unroll
            for (int c = 0; c < 4; c++) sacc[j][c] = 0.f;

#pragma unroll
        for (int ks = 0; ks < 4; ks++) {
            const int cq = 2 * ks + qc8h;
            const int ck = 2 * ks + kc8h;
            uint32_t qf[4];
            const uint32_t qoff = (uint32_t)(cq * 16 + rA8) * 128 + ((rA7 ^ cq) * 16);
            ldm4(qf, Qs + qoff);
#pragma unroll
            for (int j = 0; j < 4; j++) {
                uint32_t kf[4];
                const int rowK = 16 * j + nKl;
                const uint32_t koff = (uint32_t)(ck * 8 + (rowK >> 3)) * 128
                                    + (((rowK & 7) ^ ck) * 16);
                ldm4(kf, Ks + koff);
                mma16816h(sacc[2 * j],     qf, kf);
                mma16816h(sacc[2 * j + 1], qf, kf + 2);
            }
        }

        float mx0 = -1e30f, mx1 = -1e30f;
#pragma unroll
        for (int j = 0; j < 8; j++) {
            int col = k0 + j * 8 + (lane & 3) * 2;
            float s0 = (col     <= row0) ? sacc[j][0] * sc2 + sl2 * (float)(col     - row0) : -1e30f;
            float s1 = (col + 1 <= row0) ? sacc[j][1] * sc2 + sl2 * (float)(col + 1 - row0) : -1e30f;
            float s2 = (col     <= row1) ? sacc[j][2] * sc2 + sl2 * (float)(col     - row1) : -1e30f;
            float s3 = (col + 1 <= row1) ? sacc[j][3] * sc2 + sl2 * (float)(col + 1 - row1) : -1e30f;
            sacc[j][0] = s0; sacc[j][1] = s1; sacc[j][2] = s2; sacc[j][3] = s3;
            mx0 = fmaxf(mx0, fmaxf(s0, s1));
            mx1 = fmaxf(mx1, fmaxf(s2, s3));
        }
        mx0 = fmaxf(mx0, __shfl_xor_sync(0xFFFFFFFFu, mx0, 1));
        mx0 = fmaxf(mx0, __shfl_xor_sync(0xFFFFFFFFu, mx0, 2));
        mx1 = fmaxf(mx1, __shfl_xor_sync(0xFFFFFFFFu, mx1, 1));
        mx1 = fmaxf(mx1, __shfl_xor_sync(0xFFFFFFFFu, mx1, 2));
        float mn0 = fmaxf(m0r, mx0), mn1 = fmaxf(m1r, mx1);
        float cr0 = exp2f(m0r - mn0), cr1 = exp2f(m1r - mn1);
        m0r = mn0; m1r = mn1;
        l0 *= cr0; l1 *= cr1;
#pragma unroll
        for (int j = 0; j < 8; j++) {
            float p0 = exp2f(sacc[j][0] - mn0);
            float p1 = exp2f(sacc[j][1] - mn0);
            float p2 = exp2f(sacc[j][2] - mn1);
            float p3 = exp2f(sacc[j][3] - mn1);
            l0 += p0 + p1; l1 += p2 + p3;
            sacc[j][0] = p0; sacc[j][1] = p1; sacc[j][2] = p2; sacc[j][3] = p3;
        }
#pragma unroll
        for (int j = 0; j < 8; j++) {
            oacc[j][0] *= cr0; oacc[j][1] *= cr0;
            oacc[j][2] *= cr1; oacc[j][3] *= cr1;
        }

        uint32_t pa[4][4];
#pragma unroll
        for (int t = 0; t < 4; t++) {
            pa[t][0] = pack_h2(sacc[2 * t][0],     sacc[2 * t][1]);
            pa[t][1] = pack_h2(sacc[2 * t][2],     sacc[2 * t][3]);
            pa[t][2] = pack_h2(sacc[2 * t + 1][0], sacc[2 * t + 1][1]);
            pa[t][3] = pack_h2(sacc[2 * t + 1][2], sacc[2 * t + 1][3]);
        }

#pragma unroll
        for (int g = 0; g < 4; g++) {
            const int cv = 2 * g + vc8h;
#pragma unroll
            for (int ks = 0; ks < 4; ks++) {
                uint32_t vf[4];
                const int rowV = 16 * ks + rVl;
                const uint32_t voff = (uint32_t)(cv * 8 + (rowV >> 3)) * 128
                                    + (((rowV & 7) ^ cv) * 16);
                ldm4t(vf, Vs + voff);
                mma16816h(oacc[2 * g],     pa[ks], vf);
                mma16816h(oacc[2 * g + 1], pa[ks], vf + 2);
            }
        }
    }

    l0 += __shfl_xor_sync(0xFFFFFFFFu, l0, 1);
    l0 += __shfl_xor_sync(0xFFFFFFFFu, l0, 2);
    l1 += __shfl_xor_sync(0xFFFFFFFFu, l1, 1);
    l1 += __shfl_xor_sync(0xFFFFFFFFu, l1, 2);
    const float iv0 = 1.0f / l0, iv1 = 1.0f / l1;
    const size_t gr0 = (rbase + row0) * C_;
    const size_t gr1 = (rbase + row1) * C_;
#pragma unroll
    for (int j = 0; j < 8; j++) {
        int col = h * DH_ + j * 8 + (lane & 3) * 2;
        *(uint32_t*)(oh + gr0 + col) = pack_h2(oacc[j][0] * iv0, oacc[j][1] * iv0);
        *(uint32_t*)(oh + gr1 + col) = pack_h2(oacc[j][2] * iv1, oacc[j][3] * iv1);
    }
}

// ---------------------------------------------------------------------------
extern "C" void kernel_launch(void* const* d_in, const int* in_sizes, int n_in,
                              void* d_out, int out_size)
{
    const float* x     = (const float*)d_in[0];
    const float* w_qkv = (const float*)d_in[1];
    const float* w_o   = (const float*)d_in[2];
    float* out = (float*)d_out;

    __half *xh, *qkvh, *wqh, *woh;
    cudaGetSymbolAddress((void**)&xh,   g_xh);
    cudaGetSymbolAddress((void**)&qkvh, g_qkvh);
    cudaGetSymbolAddress((void**)&wqh,  g_wqh);
    cudaGetSymbolAddress((void**)&woh,  g_woh);

    cudaFuncSetAttribute(gemm_mma, cudaFuncAttributeMaxDynamicSharedMemorySize, GEMM_SMEM);
    cudaFuncSetAttribute(attn_mma, cudaFuncAttributeMaxDynamicSharedMemorySize, ATT_SMEM);

    // 0) fp16 conversions
    to_h16<<<(M_ * C_ + 255) / 256, 256>>>(x, xh, M_ * C_);
    transT_h16<<<dim3(C3_ / 32, C_ / 32), dim3(32, 8)>>>(w_qkv, wqh, C_, C3_);
    transT_h16<<<dim3(C_ / 32,  C_ / 32), dim3(32, 8)>>>(w_o,   woh, C_, C_);

    // 1) qkv = x @ w_qkv  (single product, fp16 out)
    gemm_mma<<<dim3(C3_ / 128, M_ / 128), 256, GEMM_SMEM>>>(
        xh, wqh, nullptr, qkvh, C3_);

    // 2) flash attention (all single product); O -> xh (fp16)
    attn_mma<<<dim3(T_ / AQT, H_, B_), 256, ATT_SMEM>>>(qkvh, xh);

    // 3) out = O @ w_o (single product, fp32 out)
    gemm_mma<<<dim3(C_ / 128, M_ / 128), 256, GEMM_SMEM>>>(
        xh, woh, out, nullptr, C_);
}